// round 3
// baseline (speedup 1.0000x reference)
#include <cuda_runtime.h>
#include <cuda_bf16.h>
#include <cstdint>
#include <cstddef>

// RNN-T beam search. B=8, T=128, H=1024, V=4096, K=5 (M = 40 hyps).
// Persistent-kernel implementation: 148 CTAs, software grid barrier,
// 5 stages per frame, fused epilogues.

#define HH   1024
#define VV   4096
#define BB   8
#define KBM  5
#define MM   40
#define TT   128
#define GRID 148
#define NEGF -3.0e38f

// ----------------------------- device state --------------------------------
__device__ float g_tnproj[BB * TT * HH];        // 4 MB
__device__ float g_Wcat[4096 * 2048];           // 33.5 MB gate-interleaved [W_ih|W_hh]
__device__ float g_blstm_p[4096];
__device__ float g_partial[32 * MM * HH];       // pn split-K partials
__device__ float g_h[2][MM * HH];
__device__ float g_c[2][MM * HH];
__device__ float g_hnew[MM * HH];
__device__ float g_cnew[MM * HH];
__device__ float g_joint[MM * HH];
__device__ float g_rmax[MM * 128];
__device__ float g_rsum[MM * 128];
__device__ float g_t5v[MM * 128 * 5];
__device__ int   g_t5i[MM * 128 * 5];
__device__ float g_scores[2][MM];
__device__ int   g_tokens[2][MM];
__device__ int   g_lens[2][MM];
__device__ int   g_preds[2][MM * TT];
__device__ unsigned int g_barcnt;
__device__ volatile unsigned int g_barphase;

__device__ __forceinline__ float sigm(float x) { return 1.0f / (1.0f + expf(-x)); }

// ----------------------------- grid barrier --------------------------------
__device__ __forceinline__ void gbar(unsigned int& ph) {
    __syncthreads();
    ph++;
    if (threadIdx.x == 0) {
        __threadfence();
        unsigned int a = atomicAdd(&g_barcnt, 1u);
        if (a == GRID - 1u) {
            g_barcnt = 0u;
            __threadfence();
            g_barphase = ph;
        } else {
            while (g_barphase < ph) __nanosleep(64);
        }
        __threadfence();
    }
    __syncthreads();
}

// ----------------------------- init ----------------------------------------
__global__ void init_state() {
    int idx = blockIdx.x * 256 + threadIdx.x;   // 160*256 = 40960
    if (idx < MM * HH) { g_h[0][idx] = 0.0f; g_c[0][idx] = 0.0f; }
    if (idx < MM) {
        g_scores[0][idx] = (idx % KBM == 0) ? 0.0f : -1e9f;
        g_tokens[0][idx] = 0;
        g_lens[0][idx]   = 0;
    }
    if (idx < MM * TT) g_preds[0][idx] = 0;
    if (idx == 0) { g_barcnt = 0u; g_barphase = 0u; }
}

// ----------------------------- weight permute -------------------------------
// g_Wcat row n' = 4u+g holds [W_ih[g*1024+u][0:1024] | W_hh[g*1024+u][0:1024]]
__global__ void permute_w(const float* __restrict__ W_ih,
                          const float* __restrict__ W_hh,
                          const float* __restrict__ b_lstm) {
    int o = blockIdx.x * 256 + threadIdx.x;     // 8192*256 = 2,097,152 float4s
    int np = o >> 9;                            // 512 float4 per 2048-row
    int q  = o & 511;
    int k  = q * 4;
    int u = np >> 2, g = np & 3;
    const float* src = (k < 1024)
        ? &W_ih[(size_t)(g * 1024 + u) * 1024 + k]
        : &W_hh[(size_t)(g * 1024 + u) * 1024 + (k - 1024)];
    *(float4*)&g_Wcat[(size_t)np * 2048 + k] = *(const float4*)src;
    if (o < 4096) {
        int uu = o >> 2, gg = o & 3;
        g_blstm_p[o] = b_lstm[gg * 1024 + uu];
    }
}

// ----------------------------- tn_proj GEMM --------------------------------
__global__ __launch_bounds__(256) void tnproj_gemm(const float* __restrict__ A,
                                                   const float* __restrict__ Bm) {
    __shared__ float As[16][65];
    __shared__ float Bs[16][64];
    int tid = threadIdx.x;
    int tx = tid & 15, ty = tid >> 4;
    int m0 = blockIdx.y * 64, n0 = blockIdx.x * 64;
    float acc[4][4];
#pragma unroll
    for (int i = 0; i < 4; i++)
#pragma unroll
        for (int j = 0; j < 4; j++) acc[i][j] = 0.0f;

    for (int kk = 0; kk < 1024; kk += 16) {
        {
            int mm = tid >> 2;
            int kq = (tid & 3) * 4;
            float4 v = *(const float4*)&A[(size_t)(m0 + mm) * 1024 + kk + kq];
            As[kq + 0][mm] = v.x; As[kq + 1][mm] = v.y;
            As[kq + 2][mm] = v.z; As[kq + 3][mm] = v.w;
        }
#pragma unroll
        for (int r = 0; r < 4; r++) {
            int idx = tid + r * 256;
            int k = idx >> 6, n = idx & 63;
            Bs[k][n] = Bm[(size_t)(kk + k) * 1024 + n0 + n];
        }
        __syncthreads();
#pragma unroll
        for (int k = 0; k < 16; k++) {
            float a[4], b[4];
#pragma unroll
            for (int i = 0; i < 4; i++) a[i] = As[k][ty + 16 * i];
#pragma unroll
            for (int j = 0; j < 4; j++) b[j] = Bs[k][tx + 16 * j];
#pragma unroll
            for (int i = 0; i < 4; i++)
#pragma unroll
                for (int j = 0; j < 4; j++) acc[i][j] += a[i] * b[j];
        }
        __syncthreads();
    }
#pragma unroll
    for (int i = 0; i < 4; i++)
#pragma unroll
        for (int j = 0; j < 4; j++)
            g_tnproj[(size_t)(m0 + ty + 16 * i) * 1024 + n0 + tx + 16 * j] = acc[i][j];
}

// ----------------------------- stage: gates + LSTM -------------------------
// block owns 32 permuted gate cols (8 hidden units x 4 gates), full K=2048.
__device__ void gates_stage(float* shA, float* shB, int blk, int cur,
                            const float* __restrict__ E) {
    float (*As)[41] = (float(*)[41])shA;
    float (*Bs)[33] = (float(*)[33])shB;
    __shared__ int s_tok[MM];
    int tid = threadIdx.x;
    if (tid < MM) s_tok[tid] = g_tokens[cur][tid];
    __syncthreads();
    int n0 = blk * 32;
    int n = tid & 31, mg = tid >> 5;
    float acc[5] = {0.f, 0.f, 0.f, 0.f, 0.f};

    for (int kc = 0; kc < 64; kc++) {
        int kbase = kc * 32;
        if (kc < 32) {
#pragma unroll
            for (int r = 0; r < 5; r++) {
                int idx = tid + r * 256;
                int m = idx >> 5, kk = idx & 31;
                As[kk][m] = E[(size_t)s_tok[m] * HH + kbase + kk];
            }
        } else {
#pragma unroll
            for (int r = 0; r < 5; r++) {
                int idx = tid + r * 256;
                int m = idx >> 5, kk = idx & 31;
                As[kk][m] = g_h[cur][m * HH + (kbase - 1024) + kk];
            }
        }
        {
            int bn = tid >> 3, kq = (tid & 7) * 4;
            float4 v = *(const float4*)&g_Wcat[(size_t)(n0 + bn) * 2048 + kbase + kq];
            Bs[kq + 0][bn] = v.x; Bs[kq + 1][bn] = v.y;
            Bs[kq + 2][bn] = v.z; Bs[kq + 3][bn] = v.w;
        }
        __syncthreads();
#pragma unroll 4
        for (int kk = 0; kk < 32; kk++) {
            float b = Bs[kk][n];
#pragma unroll
            for (int i = 0; i < 5; i++) acc[i] = fmaf(As[kk][mg * 5 + i], b, acc[i]);
        }
        __syncthreads();
    }
    // LSTM epilogue: cols 4u..4u+3 = gates i,f,g,o of hidden unit u.
    float bias = g_blstm_p[n0 + n];
    int colg = n & 3;
    int u = (n0 + n) >> 2;
    int base = n & ~3;
#pragma unroll
    for (int i = 0; i < 5; i++) {
        float g = acc[i] + bias;
        float gi = __shfl_sync(0xffffffffu, g, base + 0);
        float gf = __shfl_sync(0xffffffffu, g, base + 1);
        float gg = __shfl_sync(0xffffffffu, g, base + 2);
        float go = __shfl_sync(0xffffffffu, g, base + 3);
        if (colg == 0) {
            int m = mg * 5 + i;
            float co = g_c[cur][m * HH + u];
            float cn = sigm(gf) * co + sigm(gi) * tanhf(gg);
            float hn = sigm(go) * tanhf(cn);
            g_cnew[m * HH + u] = cn;
            g_hnew[m * HH + u] = hn;
        }
    }
}

// ----------------------------- stage: pn GEMM (split-K 32) ------------------
__device__ void pn_stage(float* shA, float* shB, int blk,
                         const float* __restrict__ Wpn) {
    float (*As)[41]  = (float(*)[41])shA;
    float (*Bs)[256] = (float(*)[256])shB;
    int tid = threadIdx.x;
    int n0 = (blk & 3) * 256;
    int s  = blk >> 2;              // k-slice 0..31
    int kl = s * 32;
    float acc[10][4];
#pragma unroll
    for (int i = 0; i < 10; i++) { acc[i][0] = acc[i][1] = acc[i][2] = acc[i][3] = 0.f; }
    int nn = tid & 63, m0 = (tid >> 6) * 10;

#pragma unroll
    for (int r = 0; r < 5; r++) {
        int i = tid + r * 256;
        int m = i >> 5, kk = i & 31;
        As[kk][m] = g_hnew[m * HH + kl + kk];
    }
    {
        int kt = tid >> 6;
        int n4 = (tid & 63) * 4;
#pragma unroll
        for (int r = 0; r < 8; r++) {
            int kk = kt + 4 * r;
            float4 v = *(const float4*)&Wpn[(size_t)(kl + kk) * HH + n0 + n4];
            *(float4*)&Bs[kk][n4] = v;
        }
    }
    __syncthreads();
#pragma unroll 4
    for (int kk = 0; kk < 32; ++kk) {
        float b0 = Bs[kk][nn], b1 = Bs[kk][nn + 64];
        float b2 = Bs[kk][nn + 128], b3 = Bs[kk][nn + 192];
#pragma unroll
        for (int i = 0; i < 10; i++) {
            float a = As[kk][m0 + i];
            acc[i][0] = fmaf(a, b0, acc[i][0]); acc[i][1] = fmaf(a, b1, acc[i][1]);
            acc[i][2] = fmaf(a, b2, acc[i][2]); acc[i][3] = fmaf(a, b3, acc[i][3]);
        }
    }
    __syncthreads();
    float* p = g_partial + (size_t)s * MM * HH;
#pragma unroll
    for (int i = 0; i < 10; i++) {
        size_t row = (size_t)(m0 + i) * HH + n0;
        p[row + nn]       = acc[i][0];
        p[row + nn + 64]  = acc[i][1];
        p[row + nn + 128] = acc[i][2];
        p[row + nn + 192] = acc[i][3];
    }
}

// ----------------------------- stage: joint reduce --------------------------
__device__ void joint_stage(const float* __restrict__ b_joint, int t, int blk) {
    for (int e = blk * 256 + threadIdx.x; e < MM * HH; e += GRID * 256) {
        int m = e >> 10, j = e & 1023;
        float v = b_joint[j];
#pragma unroll
        for (int s = 0; s < 32; s++) v += g_partial[(size_t)s * MM * HH + e];
        int b = m / KBM;
        v += g_tnproj[((size_t)b * TT + t) * HH + j];
        g_joint[e] = tanhf(v);
    }
}

// ----------------------------- stage: out GEMM + stats ----------------------
__device__ void out_stage(float* shA, float* shB, int blk,
                          const float* __restrict__ Wout,
                          const float* __restrict__ bout) {
    float (*As)[41] = (float(*)[41])shA;
    float (*Bs)[33] = (float(*)[33])shB;
    int tid = threadIdx.x;
    int n0 = blk * 32;
    int n = tid & 31, mg = tid >> 5;
    float acc[5] = {0.f, 0.f, 0.f, 0.f, 0.f};

    for (int kc = 0; kc < 32; kc++) {
        int kbase = kc * 32;
#pragma unroll
        for (int r = 0; r < 5; r++) {
            int idx = tid + r * 256;
            int m = idx >> 5, kk = idx & 31;
            As[kk][m] = g_joint[m * HH + kbase + kk];
        }
        {
            int kk8 = tid >> 3, nq = (tid & 7) * 4;
            float4 v = *(const float4*)&Wout[(size_t)(kbase + kk8) * VV + n0 + nq];
            Bs[kk8][nq + 0] = v.x; Bs[kk8][nq + 1] = v.y;
            Bs[kk8][nq + 2] = v.z; Bs[kk8][nq + 3] = v.w;
        }
        __syncthreads();
#pragma unroll 4
        for (int kk = 0; kk < 32; kk++) {
            float b = Bs[kk][n];
#pragma unroll
            for (int i = 0; i < 5; i++) acc[i] = fmaf(As[kk][mg * 5 + i], b, acc[i]);
        }
        __syncthreads();
    }
    // stats epilogue: per row — slice max, sumexp, top-5 (val desc, col asc)
    float bias = bout[n0 + n];
    unsigned full = 0xffffffffu;
#pragma unroll
    for (int i = 0; i < 5; i++) {
        int row = mg * 5 + i;
        float v = acc[i] + bias;
        float mx = v;
#pragma unroll
        for (int off = 16; off > 0; off >>= 1)
            mx = fmaxf(mx, __shfl_xor_sync(full, mx, off));
        float se = expf(v - mx);
#pragma unroll
        for (int off = 16; off > 0; off >>= 1)
            se += __shfl_xor_sync(full, se, off);
        bool chosen = false;
        for (int j = 0; j < 5; j++) {
            float cv = chosen ? NEGF : v;
            int ci = n;
#pragma unroll
            for (int off = 16; off > 0; off >>= 1) {
                float ov = __shfl_xor_sync(full, cv, off);
                int   oi = __shfl_xor_sync(full, ci, off);
                if (ov > cv || (ov == cv && oi < ci)) { cv = ov; ci = oi; }
            }
            if (n == 0) {
                g_t5v[row * 640 + blk * 5 + j] = cv;
                g_t5i[row * 640 + blk * 5 + j] = n0 + ci;
            }
            if (n == ci) chosen = true;
        }
        if (n == 0) {
            g_rmax[row * 128 + blk] = mx;
            g_rsum[row * 128 + blk] = se;
        }
    }
}

// ----------------------------- stage: topk + update -------------------------
__device__ void topk_stage(int b, int cur) {
    int tid = threadIdx.x;
    int nxt = cur ^ 1;
    int warp = tid >> 5, lane = tid & 31;
    unsigned full = 0xffffffffu;
    __shared__ float t_rv[25];
    __shared__ int   t_ri[25];
    __shared__ float t_fv[KBM];
    __shared__ int   t_fi[KBM];
    __shared__ int   t_par[KBM], t_tok[KBM], t_blk[KBM], t_plen[KBM];

    if (warp < KBM) {
        int row = b * KBM + warp;
        // --- LSE combine over 128 slices ---
        float rm[4], rs[4];
#pragma unroll
        for (int q = 0; q < 4; q++) {
            rm[q] = g_rmax[row * 128 + lane * 4 + q];
            rs[q] = g_rsum[row * 128 + lane * 4 + q];
        }
        float M = fmaxf(fmaxf(rm[0], rm[1]), fmaxf(rm[2], rm[3]));
#pragma unroll
        for (int off = 16; off > 0; off >>= 1)
            M = fmaxf(M, __shfl_xor_sync(full, M, off));
        float S = 0.f;
#pragma unroll
        for (int q = 0; q < 4; q++) S += rs[q] * expf(rm[q] - M);
#pragma unroll
        for (int off = 16; off > 0; off >>= 1)
            S += __shfl_xor_sync(full, S, off);
        float lse = M + logf(S);
        float sc = g_scores[cur][row];
        // --- per-row top5 over 640 slice candidates ---
        int selg[KBM];
        float selv[KBM];
        for (int j = 0; j < KBM; j++) {
            float bv = NEGF; int bi = 0x7fffffff;
            for (int q = 0; q < 20; q++) {
                int c = lane * 20 + q;
                int gidx = warp * 4096 + g_t5i[row * 640 + c];
                bool skip = false;
                for (int p = 0; p < j; p++) if (gidx == selg[p]) skip = true;
                if (skip) continue;
                float adj = sc + g_t5v[row * 640 + c] - lse;
                if (adj > bv || (adj == bv && gidx < bi)) { bv = adj; bi = gidx; }
            }
#pragma unroll
            for (int off = 16; off > 0; off >>= 1) {
                float ov = __shfl_xor_sync(full, bv, off);
                int   oi = __shfl_xor_sync(full, bi, off);
                if (ov > bv || (ov == bv && oi < bi)) { bv = ov; bi = oi; }
            }
            selg[j] = bi; selv[j] = bv;
        }
        if (lane == 0) {
#pragma unroll
            for (int j = 0; j < KBM; j++) {
                t_rv[warp * KBM + j] = selv[j];
                t_ri[warp * KBM + j] = selg[j];
            }
        }
    }
    __syncthreads();
    // --- final top5 of 25 (warp 0) ---
    if (warp == 0) {
        float v  = (lane < 25) ? t_rv[lane] : NEGF;
        int   gi = (lane < 25) ? t_ri[lane] : 0x7fffffff;
        bool chosen = false;
        for (int j = 0; j < KBM; j++) {
            float cv = chosen ? NEGF : v;
            int ci = gi;
#pragma unroll
            for (int off = 16; off > 0; off >>= 1) {
                float ov = __shfl_xor_sync(full, cv, off);
                int   oi = __shfl_xor_sync(full, ci, off);
                if (ov > cv || (ov == cv && oi < ci)) { cv = ov; ci = oi; }
            }
            if (lane == 0) { t_fv[j] = cv; t_fi[j] = ci; }
            if (gi == ci) chosen = true;
        }
    }
    __syncthreads();
    // --- decode winners ---
    if (tid < KBM) {
        int idx = t_fi[tid];
        int par = idx >> 12, tok = idx & 4095;
        int blank = (tok == 0);
        int p = b * KBM + par, mn = b * KBM + tid;
        t_par[tid] = par; t_tok[tid] = tok; t_blk[tid] = blank;
        int pl = g_lens[cur][p];
        t_plen[tid] = pl;
        g_scores[nxt][mn] = t_fv[tid];
        g_lens[nxt][mn]   = pl + (blank ? 0 : 1);
        g_tokens[nxt][mn] = blank ? g_tokens[cur][p] : tok;
    }
    __syncthreads();
    // --- gather h/c/preds ---
    for (int j = 0; j < KBM; j++) {
        int p = b * KBM + t_par[j], mn = b * KBM + j;
        bool blank = (t_blk[j] != 0);
        const float* hs = blank ? &g_h[cur][p * HH] : &g_hnew[p * HH];
        const float* cs = blank ? &g_c[cur][p * HH] : &g_cnew[p * HH];
        for (int i = tid; i < HH; i += 256) {
            g_h[nxt][mn * HH + i] = hs[i];
            g_c[nxt][mn * HH + i] = cs[i];
        }
        for (int i = tid; i < TT; i += 256) {
            int v = g_preds[cur][p * TT + i];
            if (!blank && i == t_plen[j]) v = t_tok[j];
            g_preds[nxt][mn * TT + i] = v;
        }
    }
}

// ----------------------------- finalize -------------------------------------
__device__ void finalize_stage(float* __restrict__ out) {
    int tid = threadIdx.x;
    __shared__ float s_norm[MM];
    __shared__ int   s_best[BB];
    if (tid < MM)
        s_norm[tid] = g_scores[0][tid] / ((float)g_lens[0][tid] + 1.0f);
    __syncthreads();
    if (tid < BB) {
        float bv = NEGF; int bj = 0;
        for (int j = 0; j < KBM; j++) {
            float v = s_norm[tid * KBM + j];
            if (v > bv) { bv = v; bj = j; }
        }
        s_best[tid] = bj;
        out[BB * TT + tid] = (float)g_lens[0][tid * KBM + bj];
    }
    if (tid < MM) out[BB * TT + BB + 1 + tid] = s_norm[tid];
    __syncthreads();
    if (tid == 0) {
        float acc = 0.0f;
        for (int b2 = 0; b2 < BB; b2++) {
            float bv = NEGF;
            for (int j = 0; j < KBM; j++) bv = fmaxf(bv, s_norm[b2 * KBM + j]);
            acc += expf(bv);
        }
        out[BB * TT + BB] = acc / (float)BB;
    }
    for (int b2 = 0; b2 < BB; b2++) {
        int m = b2 * KBM + s_best[b2];
        for (int i = tid; i < TT; i += 256)
            out[b2 * TT + i] = (float)g_preds[0][m * TT + i];
    }
}

// ----------------------------- persistent kernel ----------------------------
__global__ __launch_bounds__(256, 1) void persist(const float* __restrict__ E,
                                                  const float* __restrict__ Wpn,
                                                  const float* __restrict__ b_joint,
                                                  const float* __restrict__ Wout,
                                                  const float* __restrict__ bout,
                                                  float* __restrict__ out) {
    __shared__ float shA[32 * 41];
    __shared__ float shB[32 * 256];
    unsigned int ph = 0;
    int blk = blockIdx.x;
    for (int t = 0; t < TT; t++) {
        int cur = t & 1;
        if (blk < 128) gates_stage(shA, shB, blk, cur, E);
        gbar(ph);
        if (blk < 128) pn_stage(shA, shB, blk, Wpn);
        gbar(ph);
        joint_stage(b_joint, t, blk);
        gbar(ph);
        if (blk < 128) out_stage(shA, shB, blk, Wout, bout);
        gbar(ph);
        if (blk < BB) topk_stage(blk, cur);
        gbar(ph);
    }
    if (blk == 0) finalize_stage(out);
}

// ----------------------------- launch ---------------------------------------
extern "C" void kernel_launch(void* const* d_in, const int* in_sizes, int n_in,
                              void* d_out, int out_size) {
    const float* tn      = (const float*)d_in[0];
    const float* E       = (const float*)d_in[1];
    const float* W_ih    = (const float*)d_in[2];
    const float* W_hh    = (const float*)d_in[3];
    const float* b_lstm  = (const float*)d_in[4];
    const float* W_tn    = (const float*)d_in[5];
    const float* W_pn    = (const float*)d_in[6];
    const float* b_joint = (const float*)d_in[7];
    const float* W_out   = (const float*)d_in[8];
    const float* b_out   = (const float*)d_in[9];
    float* out = (float*)d_out;

    init_state<<<160, 256>>>();
    permute_w<<<8192, 256>>>(W_ih, W_hh, b_lstm);
    tnproj_gemm<<<dim3(16, 16), 256>>>(tn, W_tn);
    persist<<<GRID, 256>>>(E, W_pn, b_joint, W_out, b_out, out);
}

// round 4
// speedup vs baseline: 1.1861x; 1.1861x over previous
#include <cuda_runtime.h>
#include <cuda_bf16.h>
#include <cstdint>
#include <cstddef>

// RNN-T beam search. B=8, T=128, H=1024, V=4096, K=5 (M = 40 hyps).
// Persistent kernel, split-K GEMMs with 5m x 8n register tiles, fused reduces.

#define HH   1024
#define VV   4096
#define BB   8
#define KBM  5
#define MM   40
#define TT   128
#define GRID 148
#define NEGF -3.0e38f

// ----------------------------- device state --------------------------------
__device__ __align__(16) float g_tnproj[BB * TT * HH];     // 4 MB
__device__ __align__(16) float g_WcatT[2048 * 4096];       // 32 MB [k][n'] gate-permuted
__device__ __align__(16) float g_blstm_p[4096];            // permuted bias [4u+g]
__device__ __align__(16) float g_bufA[8 * MM * VV];        // gates partials, then out partials
__device__ __align__(16) float g_bufB[32 * MM * HH];       // pn partials
__device__ __align__(16) float g_h[2][MM * HH];
__device__ __align__(16) float g_c[2][MM * HH];
__device__ __align__(16) float g_hnew[MM * HH];
__device__ __align__(16) float g_cnew[MM * HH];
__device__ __align__(16) float g_joint[MM * HH];
__device__ float g_scores[2][MM];
__device__ int   g_tokens[2][MM];
__device__ int   g_lens[2][MM];
__device__ int   g_preds[2][MM * TT];
__device__ unsigned int g_barcnt;

__device__ __forceinline__ float sigm(float x) { return 1.0f / (1.0f + expf(-x)); }

// ---------------------- grid barrier (monotonic counter) --------------------
__device__ __forceinline__ void gbar(unsigned int& ph) {
    __syncthreads();
    ph++;
    if (threadIdx.x == 0) {
        __threadfence();
        atomicAdd(&g_barcnt, 1u);
        unsigned int target = ph * (unsigned int)GRID;
        while (*(volatile unsigned int*)&g_barcnt < target) __nanosleep(32);
        __threadfence();
    }
    __syncthreads();
}

// ----------------------------- init ----------------------------------------
__global__ void init_state(const float* __restrict__ b_lstm) {
    int idx = blockIdx.x * 256 + threadIdx.x;   // 160*256 = 40960
    if (idx < MM * HH) { g_h[0][idx] = 0.0f; g_c[0][idx] = 0.0f; }
    if (idx < MM) {
        g_scores[0][idx] = (idx % KBM == 0) ? 0.0f : -1e9f;
        g_tokens[0][idx] = 0;
        g_lens[0][idx]   = 0;
    }
    if (idx < MM * TT) g_preds[0][idx] = 0;
    if (idx < 4096) g_blstm_p[idx] = b_lstm[(idx & 3) * 1024 + (idx >> 2)];
    if (idx == 0) g_barcnt = 0u;
}

// --------------------- weight transpose + gate permute ----------------------
// g_WcatT[k][n'], n' = 4u+g: k<1024 -> W_ih[g*1024+u][k], else W_hh[...][k-1024]
__global__ void permute_w(const float* __restrict__ Wih,
                          const float* __restrict__ Whh) {
    __shared__ float tile[32][33];
    int x = threadIdx.x, y0 = threadIdx.y;
    int kt = blockIdx.x * 32, nt = blockIdx.y * 32;
#pragma unroll
    for (int yy = 0; yy < 32; yy += 8) {
        int np = nt + y0 + yy;
        int row = (np & 3) * 1024 + (np >> 2);
        int k = kt + x;
        float v = (k < 1024) ? Wih[(size_t)row * 1024 + k]
                             : Whh[(size_t)row * 1024 + k - 1024];
        tile[y0 + yy][x] = v;
    }
    __syncthreads();
#pragma unroll
    for (int yy = 0; yy < 32; yy += 8) {
        int k = kt + y0 + yy;
        int np = nt + x;
        g_WcatT[(size_t)k * 4096 + np] = tile[x][y0 + yy];
    }
}

// ----------------------------- tn_proj GEMM --------------------------------
__global__ __launch_bounds__(256) void tnproj_gemm(const float* __restrict__ A,
                                                   const float* __restrict__ Bm) {
    __shared__ float As[16][65];
    __shared__ float Bs[16][64];
    int tid = threadIdx.x;
    int tx = tid & 15, ty = tid >> 4;
    int m0 = blockIdx.y * 64, n0 = blockIdx.x * 64;
    float acc[4][4];
#pragma unroll
    for (int i = 0; i < 4; i++)
#pragma unroll
        for (int j = 0; j < 4; j++) acc[i][j] = 0.0f;
    for (int kk = 0; kk < 1024; kk += 16) {
        {
            int mm = tid >> 2;
            int kq = (tid & 3) * 4;
            float4 v = *(const float4*)&A[(size_t)(m0 + mm) * 1024 + kk + kq];
            As[kq + 0][mm] = v.x; As[kq + 1][mm] = v.y;
            As[kq + 2][mm] = v.z; As[kq + 3][mm] = v.w;
        }
#pragma unroll
        for (int r = 0; r < 4; r++) {
            int idx = tid + r * 256;
            int k = idx >> 6, n = idx & 63;
            Bs[k][n] = Bm[(size_t)(kk + k) * 1024 + n0 + n];
        }
        __syncthreads();
#pragma unroll
        for (int k = 0; k < 16; k++) {
            float a[4], b[4];
#pragma unroll
            for (int i = 0; i < 4; i++) a[i] = As[k][ty + 16 * i];
#pragma unroll
            for (int j = 0; j < 4; j++) b[j] = Bs[k][tx + 16 * j];
#pragma unroll
            for (int i = 0; i < 4; i++)
#pragma unroll
                for (int j = 0; j < 4; j++) acc[i][j] += a[i] * b[j];
        }
        __syncthreads();
    }
#pragma unroll
    for (int i = 0; i < 4; i++)
#pragma unroll
        for (int j = 0; j < 4; j++)
            g_tnproj[(size_t)(m0 + ty + 16 * i) * 1024 + n0 + tx + 16 * j] = acc[i][j];
}

// =========================== persistent stages ==============================
// pool layout for GEMM stages: As = pool[0..1311] as [32][41], Bs = pool+1312 as [32][256]

// gates: 16 col-blocks x 8 k-splits = 128 CTAs. C[40 x 256], K=256 per CTA.
__device__ void gates_stage(float* pool, int blk, int cur, const float* __restrict__ E) {
    float (*As)[41]  = (float(*)[41])pool;
    float (*Bs)[256] = (float(*)[256])(pool + 1312);
    __shared__ int s_tok[MM];
    int tid = threadIdx.x;
    int cb = blk & 15, sp = blk >> 4;
    int n0 = cb * 256, kb0 = sp * 256;
    if (tid < MM) s_tok[tid] = g_tokens[cur][tid];
    __syncthreads();
    float acc[5][8];
#pragma unroll
    for (int i = 0; i < 5; i++)
#pragma unroll
        for (int j = 0; j < 8; j++) acc[i][j] = 0.0f;
    int nn = tid & 31, mg = tid >> 5;

    for (int it = 0; it < 8; it++) {
        int kg = kb0 + it * 32;
#pragma unroll
        for (int r = 0; r < 5; r++) {
            int idx = tid + r * 256;
            int m = idx >> 5, kk = idx & 31;
            int k = kg + kk;
            As[kk][m] = (sp < 4) ? E[(size_t)s_tok[m] * HH + k]
                                 : g_h[cur][m * HH + (k - 1024)];
        }
#pragma unroll
        for (int r = 0; r < 8; r++) {
            int idx = tid + r * 256;
            int kk = idx >> 6, nq = (idx & 63) * 4;
            *(float4*)&Bs[kk][nq] = *(const float4*)&g_WcatT[(size_t)(kg + kk) * 4096 + n0 + nq];
        }
        __syncthreads();
#pragma unroll 4
        for (int kk = 0; kk < 32; kk++) {
            float b[8], a[5];
#pragma unroll
            for (int j = 0; j < 8; j++) b[j] = Bs[kk][nn + 32 * j];
#pragma unroll
            for (int i = 0; i < 5; i++) a[i] = As[kk][mg * 5 + i];
#pragma unroll
            for (int i = 0; i < 5; i++)
#pragma unroll
                for (int j = 0; j < 8; j++) acc[i][j] = fmaf(a[i], b[j], acc[i][j]);
        }
        __syncthreads();
    }
    float* p = g_bufA + (size_t)sp * MM * 4096;
#pragma unroll
    for (int i = 0; i < 5; i++)
#pragma unroll
        for (int j = 0; j < 8; j++)
            p[(mg * 5 + i) * 4096 + n0 + 32 * j + nn] = acc[i][j];
}

// pn: 4 col-blocks x 32 k-splits = 128 CTAs. Prologue: LSTM reduce for own k-slice.
__device__ void pn_stage(float* pool, int blk, int cur, const float* __restrict__ Wpn) {
    float (*As)[41]  = (float(*)[41])pool;
    float (*Bs)[256] = (float(*)[256])(pool + 1312);
    int tid = threadIdx.x;
    int cb = blk & 3, s = blk >> 2;
    int n0 = cb * 256, kl = s * 32;

    // --- LSTM prologue: hnew for (m, u=kl..kl+31) -> As[kk][m] ---
#pragma unroll
    for (int r = 0; r < 5; r++) {
        int idx = tid + r * 256;
        int m = idx >> 5, kk = idx & 31;
        int u = kl + kk;
        float4 s4 = make_float4(0.f, 0.f, 0.f, 0.f);
#pragma unroll
        for (int sp = 0; sp < 8; sp++) {
            float4 q = *(const float4*)&g_bufA[(size_t)sp * MM * 4096 + m * 4096 + 4 * u];
            s4.x += q.x; s4.y += q.y; s4.z += q.z; s4.w += q.w;
        }
        float4 bb = *(const float4*)&g_blstm_p[4 * u];
        float gi = s4.x + bb.x, gf = s4.y + bb.y, gg = s4.z + bb.z, go = s4.w + bb.w;
        float co = g_c[cur][m * HH + u];
        float cn = sigm(gf) * co + sigm(gi) * tanhf(gg);
        float hn = sigm(go) * tanhf(cn);
        As[kk][m] = hn;
        if (cb == 0) { g_hnew[m * HH + u] = hn; g_cnew[m * HH + u] = cn; }
    }
    // --- Bs load: Wpn rows kl..kl+31, cols n0..n0+255 ---
#pragma unroll
    for (int r = 0; r < 8; r++) {
        int idx = tid + r * 256;
        int kk = idx >> 6, nq = (idx & 63) * 4;
        *(float4*)&Bs[kk][nq] = *(const float4*)&Wpn[(size_t)(kl + kk) * HH + n0 + nq];
    }
    __syncthreads();
    float acc[5][8];
#pragma unroll
    for (int i = 0; i < 5; i++)
#pragma unroll
        for (int j = 0; j < 8; j++) acc[i][j] = 0.0f;
    int nn = tid & 31, mg = tid >> 5;
#pragma unroll 4
    for (int kk = 0; kk < 32; kk++) {
        float b[8], a[5];
#pragma unroll
        for (int j = 0; j < 8; j++) b[j] = Bs[kk][nn + 32 * j];
#pragma unroll
        for (int i = 0; i < 5; i++) a[i] = As[kk][mg * 5 + i];
#pragma unroll
        for (int i = 0; i < 5; i++)
#pragma unroll
            for (int j = 0; j < 8; j++) acc[i][j] = fmaf(a[i], b[j], acc[i][j]);
    }
    float* p = g_bufB + (size_t)s * MM * HH;
#pragma unroll
    for (int i = 0; i < 5; i++)
#pragma unroll
        for (int j = 0; j < 8; j++)
            p[(mg * 5 + i) * HH + n0 + 32 * j + nn] = acc[i][j];
}

// joint: all CTAs, reduce 32 pn partials + bias + tnproj -> tanh
__device__ void joint_stage(const float* __restrict__ b_joint, int t, int blk) {
    for (int e = blk * 256 + threadIdx.x; e < MM * HH; e += GRID * 256) {
        int m = e >> 10, j = e & 1023;
        float v = b_joint[j];
#pragma unroll
        for (int s = 0; s < 32; s++) v += g_bufB[(size_t)s * MM * HH + e];
        int b = m / KBM;
        v += g_tnproj[((size_t)b * TT + t) * HH + j];
        g_joint[e] = tanhf(v);
    }
}

// out: 16 col-blocks x 8 k-splits(128) = 128 CTAs. Writes partials to bufA.
__device__ void out_stage(float* pool, int blk, const float* __restrict__ Wout) {
    float (*As)[41]  = (float(*)[41])pool;
    float (*Bs)[256] = (float(*)[256])(pool + 1312);
    int tid = threadIdx.x;
    int cb = blk & 15, sp = blk >> 4;
    int n0 = cb * 256, kb0 = sp * 128;
    float acc[5][8];
#pragma unroll
    for (int i = 0; i < 5; i++)
#pragma unroll
        for (int j = 0; j < 8; j++) acc[i][j] = 0.0f;
    int nn = tid & 31, mg = tid >> 5;

    for (int it = 0; it < 4; it++) {
        int kg = kb0 + it * 32;
#pragma unroll
        for (int r = 0; r < 5; r++) {
            int idx = tid + r * 256;
            int m = idx >> 5, kk = idx & 31;
            As[kk][m] = g_joint[m * HH + kg + kk];
        }
#pragma unroll
        for (int r = 0; r < 8; r++) {
            int idx = tid + r * 256;
            int kk = idx >> 6, nq = (idx & 63) * 4;
            *(float4*)&Bs[kk][nq] = *(const float4*)&Wout[(size_t)(kg + kk) * VV + n0 + nq];
        }
        __syncthreads();
#pragma unroll 4
        for (int kk = 0; kk < 32; kk++) {
            float b[8], a[5];
#pragma unroll
            for (int j = 0; j < 8; j++) b[j] = Bs[kk][nn + 32 * j];
#pragma unroll
            for (int i = 0; i < 5; i++) a[i] = As[kk][mg * 5 + i];
#pragma unroll
            for (int i = 0; i < 5; i++)
#pragma unroll
                for (int j = 0; j < 8; j++) acc[i][j] = fmaf(a[i], b[j], acc[i][j]);
        }
        __syncthreads();
    }
    float* p = g_bufA + (size_t)sp * MM * VV;
#pragma unroll
    for (int i = 0; i < 5; i++)
#pragma unroll
        for (int j = 0; j < 8; j++)
            p[(mg * 5 + i) * VV + n0 + 32 * j + nn] = acc[i][j];
}

// topk: 8 CTAs (one per batch). Stats over 640 (row,slice) tasks, then merge,
// state update and h/c/preds gather.
__device__ void topk_stage(float* pool, int b, int cur, const float* __restrict__ bout) {
    int tid = threadIdx.x;
    int nxt = cur ^ 1;
    int warp = tid >> 5, lane = tid & 31;
    unsigned full = 0xffffffffu;
    float* s_rmax = pool;                 // [5*128]
    float* s_rsum = pool + 640;           // [5*128]
    float* s_t5v  = pool + 1280;          // [5*640]
    int*   s_t5i  = (int*)(pool + 4480);  // [5*640]
    __shared__ float t_rv[25];
    __shared__ int   t_ri[25];
    __shared__ float t_fv[KBM];
    __shared__ int   t_fi[KBM];
    __shared__ int   t_par[KBM], t_tok[KBM], t_blk2[KBM], t_plen[KBM];

    // --- stats: per (row, 32-col slice): max, sumexp, top-5 ---
    for (int tk = warp; tk < 640; tk += 8) {
        int r = tk >> 7, sl = tk & 127;
        int col = sl * 32 + lane;
        int row = b * KBM + r;
        float v = bout[col];
#pragma unroll
        for (int sp = 0; sp < 8; sp++)
            v += g_bufA[(size_t)sp * MM * VV + (size_t)row * VV + col];
        float mx = v;
#pragma unroll
        for (int off = 16; off > 0; off >>= 1)
            mx = fmaxf(mx, __shfl_xor_sync(full, mx, off));
        float se = expf(v - mx);
#pragma unroll
        for (int off = 16; off > 0; off >>= 1)
            se += __shfl_xor_sync(full, se, off);
        bool chosen = false;
        for (int j = 0; j < KBM; j++) {
            float cv = chosen ? NEGF : v;
            int ci = col;
#pragma unroll
            for (int off = 16; off > 0; off >>= 1) {
                float ov = __shfl_xor_sync(full, cv, off);
                int   oi = __shfl_xor_sync(full, ci, off);
                if (ov > cv || (ov == cv && oi < ci)) { cv = ov; ci = oi; }
            }
            if (lane == 0) {
                s_t5v[r * 640 + sl * 5 + j] = cv;
                s_t5i[r * 640 + sl * 5 + j] = ci;
            }
            if (col == ci) chosen = true;
        }
        if (lane == 0) { s_rmax[r * 128 + sl] = mx; s_rsum[r * 128 + sl] = se; }
    }
    __syncthreads();

    // --- per-row merge: LSE combine + top5 of 640 (warps 0..4) ---
    if (warp < KBM) {
        int row = b * KBM + warp;
        float rm[4], rs[4];
#pragma unroll
        for (int q = 0; q < 4; q++) {
            rm[q] = s_rmax[warp * 128 + lane * 4 + q];
            rs[q] = s_rsum[warp * 128 + lane * 4 + q];
        }
        float M = fmaxf(fmaxf(rm[0], rm[1]), fmaxf(rm[2], rm[3]));
#pragma unroll
        for (int off = 16; off > 0; off >>= 1)
            M = fmaxf(M, __shfl_xor_sync(full, M, off));
        float S = 0.f;
#pragma unroll
        for (int q = 0; q < 4; q++) S += rs[q] * expf(rm[q] - M);
#pragma unroll
        for (int off = 16; off > 0; off >>= 1)
            S += __shfl_xor_sync(full, S, off);
        float lse = M + logf(S);
        float sc = g_scores[cur][row];
        int selg[KBM]; float selv[KBM];
        for (int j = 0; j < KBM; j++) {
            float bv = NEGF; int bi = 0x7fffffff;
            for (int q = 0; q < 20; q++) {
                int c = lane * 20 + q;
                int gidx = warp * 4096 + s_t5i[warp * 640 + c];
                bool skip = false;
                for (int p = 0; p < j; p++) if (gidx == selg[p]) skip = true;
                if (skip) continue;
                float adj = sc + s_t5v[warp * 640 + c] - lse;
                if (adj > bv || (adj == bv && gidx < bi)) { bv = adj; bi = gidx; }
            }
#pragma unroll
            for (int off = 16; off > 0; off >>= 1) {
                float ov = __shfl_xor_sync(full, bv, off);
                int   oi = __shfl_xor_sync(full, bi, off);
                if (ov > bv || (ov == bv && oi < bi)) { bv = ov; bi = oi; }
            }
            selg[j] = bi; selv[j] = bv;
        }
        if (lane == 0) {
#pragma unroll
            for (int j = 0; j < KBM; j++) {
                t_rv[warp * KBM + j] = selv[j];
                t_ri[warp * KBM + j] = selg[j];
            }
        }
    }
    __syncthreads();
    // --- final top5 of 25 ---
    if (warp == 0) {
        float v  = (lane < 25) ? t_rv[lane] : NEGF;
        int   gi = (lane < 25) ? t_ri[lane] : 0x7fffffff;
        bool chosen = false;
        for (int j = 0; j < KBM; j++) {
            float cv = chosen ? NEGF : v;
            int ci = gi;
#pragma unroll
            for (int off = 16; off > 0; off >>= 1) {
                float ov = __shfl_xor_sync(full, cv, off);
                int   oi = __shfl_xor_sync(full, ci, off);
                if (ov > cv || (ov == cv && oi < ci)) { cv = ov; ci = oi; }
            }
            if (lane == 0) { t_fv[j] = cv; t_fi[j] = ci; }
            if (gi == ci) chosen = true;
        }
    }
    __syncthreads();
    if (tid < KBM) {
        int idx = t_fi[tid];
        int par = idx >> 12, tok = idx & 4095;
        int blank = (tok == 0);
        int p = b * KBM + par, mn = b * KBM + tid;
        t_par[tid] = par; t_tok[tid] = tok; t_blk2[tid] = blank;
        int pl = g_lens[cur][p];
        t_plen[tid] = pl;
        g_scores[nxt][mn] = t_fv[tid];
        g_lens[nxt][mn]   = pl + (blank ? 0 : 1);
        g_tokens[nxt][mn] = blank ? g_tokens[cur][p] : tok;
    }
    __syncthreads();
    for (int j = 0; j < KBM; j++) {
        int p = b * KBM + t_par[j], mn = b * KBM + j;
        bool blank = (t_blk2[j] != 0);
        const float* hs = blank ? &g_h[cur][p * HH] : &g_hnew[p * HH];
        const float* cs = blank ? &g_c[cur][p * HH] : &g_cnew[p * HH];
        for (int i = tid; i < HH; i += 256) {
            g_h[nxt][mn * HH + i] = hs[i];
            g_c[nxt][mn * HH + i] = cs[i];
        }
        for (int i = tid; i < TT; i += 256) {
            int v = g_preds[cur][p * TT + i];
            if (!blank && i == t_plen[j]) v = t_tok[j];
            g_preds[nxt][mn * TT + i] = v;
        }
    }
}

// ----------------------------- finalize -------------------------------------
__device__ void finalize_stage(float* __restrict__ out) {
    int tid = threadIdx.x;
    __shared__ float s_norm[MM];
    __shared__ int   s_best[BB];
    if (tid < MM)
        s_norm[tid] = g_scores[0][tid] / ((float)g_lens[0][tid] + 1.0f);
    __syncthreads();
    if (tid < BB) {
        float bv = NEGF; int bj = 0;
        for (int j = 0; j < KBM; j++) {
            float v = s_norm[tid * KBM + j];
            if (v > bv) { bv = v; bj = j; }
        }
        s_best[tid] = bj;
        out[BB * TT + tid] = (float)g_lens[0][tid * KBM + bj];
    }
    if (tid < MM) out[BB * TT + BB + 1 + tid] = s_norm[tid];
    __syncthreads();
    if (tid == 0) {
        float acc = 0.0f;
        for (int b2 = 0; b2 < BB; b2++) {
            float bv = NEGF;
            for (int j = 0; j < KBM; j++) bv = fmaxf(bv, s_norm[b2 * KBM + j]);
            acc += expf(bv);
        }
        out[BB * TT + BB] = acc / (float)BB;
    }
    for (int b2 = 0; b2 < BB; b2++) {
        int m = b2 * KBM + s_best[b2];
        for (int i = tid; i < TT; i += 256)
            out[b2 * TT + i] = (float)g_preds[0][m * TT + i];
    }
}

// ----------------------------- persistent kernel ----------------------------
__global__ __launch_bounds__(256) void persist(const float* __restrict__ E,
                                               const float* __restrict__ Wpn,
                                               const float* __restrict__ b_joint,
                                               const float* __restrict__ Wout,
                                               const float* __restrict__ bout,
                                               float* __restrict__ out) {
    __shared__ float pool[9504];   // As[32][41] + Bs[32][256]; reused by topk
    unsigned int ph = 0;
    int blk = blockIdx.x;
    for (int t = 0; t < TT; t++) {
        int cur = t & 1;
        if (blk < 128) gates_stage(pool, blk, cur, E);
        gbar(ph);
        if (blk < 128) pn_stage(pool, blk, cur, Wpn);
        gbar(ph);
        joint_stage(b_joint, t, blk);
        gbar(ph);
        if (blk < 128) out_stage(pool, blk, Wout);
        gbar(ph);
        if (blk < BB) topk_stage(pool, blk, cur, bout);
        gbar(ph);
    }
    if (blk == 0) finalize_stage(out);
}

// ----------------------------- launch ---------------------------------------
extern "C" void kernel_launch(void* const* d_in, const int* in_sizes, int n_in,
                              void* d_out, int out_size) {
    const float* tn      = (const float*)d_in[0];
    const float* E       = (const float*)d_in[1];
    const float* W_ih    = (const float*)d_in[2];
    const float* W_hh    = (const float*)d_in[3];
    const float* b_lstm  = (const float*)d_in[4];
    const float* W_tn    = (const float*)d_in[5];
    const float* W_pn    = (const float*)d_in[6];
    const float* b_joint = (const float*)d_in[7];
    const float* W_out   = (const float*)d_in[8];
    const float* b_out   = (const float*)d_in[9];
    float* out = (float*)d_out;

    init_state<<<160, 256>>>(b_lstm);
    permute_w<<<dim3(64, 128), dim3(32, 8)>>>(W_ih, W_hh);
    tnproj_gemm<<<dim3(16, 16), 256>>>(tn, W_tn);
    persist<<<GRID, 256>>>(E, W_pn, b_joint, W_out, b_out, out);
}

// round 5
// speedup vs baseline: 2.7304x; 2.3020x over previous
#include <cuda_runtime.h>
#include <cuda_bf16.h>
#include <cstdint>
#include <cstddef>

// RNN-T beam search. B=8, T=128, H=1024, V=4096, K=5 (M = 40 hyps).
// Persistent kernel, 2 CTAs/SM, cp.async double-buffered split-K GEMMs.

#define HH   1024
#define VV   4096
#define BB   8
#define KBM  5
#define MM   40
#define TT   128
#define GRID_ALL 296
#define NEGF -3.0e38f

// ----------------------------- device state --------------------------------
__device__ __align__(16) float g_tnproj[BB * TT * HH];     // 4 MB
__device__ __align__(16) float g_WcatT[2048 * 4096];       // 32 MB [k][n'] gate-permuted
__device__ __align__(16) float g_blstm_p[4096];            // permuted bias [4u+g]
__device__ __align__(16) float g_bufA[16 * MM * VV];       // gates/out partials (16 slices)
__device__ __align__(16) float g_bufB[32 * MM * HH];       // pn partials
__device__ __align__(16) float g_h[2][MM * HH];
__device__ __align__(16) float g_c[2][MM * HH];
__device__ __align__(16) float g_hnew[MM * HH];
__device__ __align__(16) float g_cnew[MM * HH];
__device__ __align__(16) float g_joint[MM * HH];
__device__ float g_rmax[MM * 128];
__device__ float g_rsum[MM * 128];
__device__ float g_t5v[MM * 640];
__device__ int   g_t5i[MM * 640];
__device__ float g_scores[2][MM];
__device__ int   g_tokens[2][MM];
__device__ int   g_lens[2][MM];
__device__ int   g_preds[2][MM * TT];
__device__ unsigned int g_barcnt;

__device__ __forceinline__ float sigm(float x) { return 1.0f / (1.0f + expf(-x)); }

// ----------------------------- cp.async helpers -----------------------------
__device__ __forceinline__ void cpa16(void* s, const void* g) {
    uint32_t sa = (uint32_t)__cvta_generic_to_shared(s);
    asm volatile("cp.async.cg.shared.global [%0], [%1], 16;" :: "r"(sa), "l"(g));
}
__device__ __forceinline__ void cpa4(void* s, const void* g) {
    uint32_t sa = (uint32_t)__cvta_generic_to_shared(s);
    asm volatile("cp.async.ca.shared.global [%0], [%1], 4;" :: "r"(sa), "l"(g));
}
#define CPA_COMMIT()  asm volatile("cp.async.commit_group;" ::: "memory")
#define CPA_WAIT(N)   asm volatile("cp.async.wait_group %0;" :: "n"(N) : "memory")

// ---------------------- grid barrier (monotonic counter) --------------------
__device__ __forceinline__ void gbar(unsigned int& ph) {
    __syncthreads();
    ph++;
    if (threadIdx.x == 0) {
        __threadfence();
        atomicAdd(&g_barcnt, 1u);          // return unused -> RED
        unsigned int target = ph * (unsigned int)GRID_ALL;
        while (*(volatile unsigned int*)&g_barcnt < target) __nanosleep(32);
        __threadfence();
    }
    __syncthreads();
}

// ----------------------------- init ----------------------------------------
__global__ void init_state(const float* __restrict__ b_lstm) {
    int idx = blockIdx.x * 256 + threadIdx.x;   // 160*256 = 40960
    if (idx < MM * HH) { g_h[0][idx] = 0.0f; g_c[0][idx] = 0.0f; }
    if (idx < MM) {
        g_scores[0][idx] = (idx % KBM == 0) ? 0.0f : -1e9f;
        g_tokens[0][idx] = 0;
        g_lens[0][idx]   = 0;
    }
    if (idx < MM * TT) g_preds[0][idx] = 0;
    if (idx < 4096) g_blstm_p[idx] = b_lstm[(idx & 3) * 1024 + (idx >> 2)];
    if (idx == 0) g_barcnt = 0u;
}

// --------------------- weight transpose + gate permute ----------------------
__global__ void permute_w(const float* __restrict__ Wih,
                          const float* __restrict__ Whh) {
    __shared__ float tile[32][33];
    int x = threadIdx.x, y0 = threadIdx.y;
    int kt = blockIdx.x * 32, nt = blockIdx.y * 32;
#pragma unroll
    for (int yy = 0; yy < 32; yy += 8) {
        int np = nt + y0 + yy;
        int row = (np & 3) * 1024 + (np >> 2);
        int k = kt + x;
        float v = (k < 1024) ? Wih[(size_t)row * 1024 + k]
                             : Whh[(size_t)row * 1024 + k - 1024];
        tile[y0 + yy][x] = v;
    }
    __syncthreads();
#pragma unroll
    for (int yy = 0; yy < 32; yy += 8) {
        int k = kt + y0 + yy;
        int np = nt + x;
        g_WcatT[(size_t)k * 4096 + np] = tile[x][y0 + yy];
    }
}

// ----------------------------- tn_proj GEMM --------------------------------
__global__ __launch_bounds__(256) void tnproj_gemm(const float* __restrict__ A,
                                                   const float* __restrict__ Bm) {
    __shared__ float As[16][65];
    __shared__ float Bs[16][64];
    int tid = threadIdx.x;
    int tx = tid & 15, ty = tid >> 4;
    int m0 = blockIdx.y * 64, n0 = blockIdx.x * 64;
    float acc[4][4];
#pragma unroll
    for (int i = 0; i < 4; i++)
#pragma unroll
        for (int j = 0; j < 4; j++) acc[i][j] = 0.0f;
    for (int kk = 0; kk < 1024; kk += 16) {
        {
            int mm = tid >> 2;
            int kq = (tid & 3) * 4;
            float4 v = *(const float4*)&A[(size_t)(m0 + mm) * 1024 + kk + kq];
            As[kq + 0][mm] = v.x; As[kq + 1][mm] = v.y;
            As[kq + 2][mm] = v.z; As[kq + 3][mm] = v.w;
        }
#pragma unroll
        for (int r = 0; r < 4; r++) {
            int idx = tid + r * 256;
            int k = idx >> 6, n = idx & 63;
            Bs[k][n] = Bm[(size_t)(kk + k) * 1024 + n0 + n];
        }
        __syncthreads();
#pragma unroll
        for (int k = 0; k < 16; k++) {
            float a[4], b[4];
#pragma unroll
            for (int i = 0; i < 4; i++) a[i] = As[k][ty + 16 * i];
#pragma unroll
            for (int j = 0; j < 4; j++) b[j] = Bs[k][tx + 16 * j];
#pragma unroll
            for (int i = 0; i < 4; i++)
#pragma unroll
                for (int j = 0; j < 4; j++) acc[i][j] += a[i] * b[j];
        }
        __syncthreads();
    }
#pragma unroll
    for (int i = 0; i < 4; i++)
#pragma unroll
        for (int j = 0; j < 4; j++)
            g_tnproj[(size_t)(m0 + ty + 16 * i) * 1024 + n0 + tx + 16 * j] = acc[i][j];
}

// =========================== persistent stages ==============================
struct Smem {
    float As[2][32][41];
    float Bs[2][32][256];
    int   tok[MM];
};

__device__ __forceinline__ void mm_compute(const float (*As)[41], const float (*Bs)[256],
                                           float acc[5][8], int nn, int mg) {
#pragma unroll 4
    for (int kk = 0; kk < 32; kk++) {
        float b[8], a[5];
#pragma unroll
        for (int j = 0; j < 8; j++) b[j] = Bs[kk][nn + 32 * j];
#pragma unroll
        for (int i = 0; i < 5; i++) a[i] = As[kk][mg * 5 + i];
#pragma unroll
        for (int i = 0; i < 5; i++)
#pragma unroll
            for (int j = 0; j < 8; j++) acc[i][j] = fmaf(a[i], b[j], acc[i][j]);
    }
}

// gates: 16 col-blocks(256) x 16 k-splits(128) = 256 CTAs, 4 chunks of 32.
__device__ void gates_stage(Smem* sm, int blk, int cur, const float* __restrict__ E) {
    int tid = threadIdx.x;
    int cb = blk & 15, sp = blk >> 4;
    int n0 = cb * 256, kb0 = sp * 128;
    if (tid < MM) sm->tok[tid] = g_tokens[cur][tid];
    __syncthreads();

    auto stage = [&](int c) {
        int kg = kb0 + c * 32;
        int buf = c & 1;
#pragma unroll
        for (int r = 0; r < 5; r++) {
            int idx = tid + r * 256;
            int m = idx >> 5, kk = idx & 31;
            const float* src = (sp < 8)
                ? &E[(size_t)sm->tok[m] * HH + kg + kk]
                : &g_h[cur][m * HH + (kg + kk - 1024)];
            cpa4(&sm->As[buf][kk][m], src);
        }
#pragma unroll
        for (int r = 0; r < 8; r++) {
            int idx = tid + r * 256;
            int kk = idx >> 6, nq = (idx & 63) * 4;
            cpa16(&sm->Bs[buf][kk][nq], &g_WcatT[(size_t)(kg + kk) * 4096 + n0 + nq]);
        }
        CPA_COMMIT();
    };

    float acc[5][8];
#pragma unroll
    for (int i = 0; i < 5; i++)
#pragma unroll
        for (int j = 0; j < 8; j++) acc[i][j] = 0.0f;
    int nn = tid & 31, mg = tid >> 5;

    stage(0);
    for (int c = 0; c < 4; c++) {
        if (c + 1 < 4) { stage(c + 1); CPA_WAIT(1); }
        else           { CPA_WAIT(0); }
        __syncthreads();
        mm_compute(sm->As[c & 1], sm->Bs[c & 1], acc, nn, mg);
        __syncthreads();
    }
    float* p = g_bufA + (size_t)sp * MM * VV;
#pragma unroll
    for (int i = 0; i < 5; i++)
#pragma unroll
        for (int j = 0; j < 8; j++)
            p[(mg * 5 + i) * VV + n0 + 32 * j + nn] = acc[i][j];
}

// pn: 4 col-blocks(256) x 32 k-splits(32) = 128 CTAs. LSTM-reduce prologue.
__device__ void pn_stage(Smem* sm, int blk, int cur, const float* __restrict__ Wpn) {
    int tid = threadIdx.x;
    int cb = blk & 3, s = blk >> 2;
    int n0 = cb * 256, kl = s * 32;

    // Bs via cp.async (overlaps with prologue compute)
#pragma unroll
    for (int r = 0; r < 8; r++) {
        int idx = tid + r * 256;
        int kk = idx >> 6, nq = (idx & 63) * 4;
        cpa16(&sm->Bs[0][kk][nq], &Wpn[(size_t)(kl + kk) * HH + n0 + nq]);
    }
    CPA_COMMIT();

    // LSTM prologue: hnew for (m, u=kl..kl+31) -> As[0][kk][m]
#pragma unroll
    for (int r = 0; r < 5; r++) {
        int idx = tid + r * 256;
        int m = idx >> 5, kk = idx & 31;
        int u = kl + kk;
        float4 s4 = make_float4(0.f, 0.f, 0.f, 0.f);
#pragma unroll
        for (int sp = 0; sp < 16; sp++) {
            float4 q = *(const float4*)&g_bufA[(size_t)sp * MM * VV + m * VV + 4 * u];
            s4.x += q.x; s4.y += q.y; s4.z += q.z; s4.w += q.w;
        }
        float4 bb = *(const float4*)&g_blstm_p[4 * u];
        float gi = s4.x + bb.x, gf = s4.y + bb.y, gg = s4.z + bb.z, go = s4.w + bb.w;
        float co = g_c[cur][m * HH + u];
        float cn = sigm(gf) * co + sigm(gi) * tanhf(gg);
        float hn = sigm(go) * tanhf(cn);
        sm->As[0][kk][m] = hn;
        if (cb == 0) { g_hnew[m * HH + u] = hn; g_cnew[m * HH + u] = cn; }
    }
    CPA_WAIT(0);
    __syncthreads();

    float acc[5][8];
#pragma unroll
    for (int i = 0; i < 5; i++)
#pragma unroll
        for (int j = 0; j < 8; j++) acc[i][j] = 0.0f;
    int nn = tid & 31, mg = tid >> 5;
    mm_compute(sm->As[0], sm->Bs[0], acc, nn, mg);
    __syncthreads();

    float* p = g_bufB + (size_t)s * MM * HH;
#pragma unroll
    for (int i = 0; i < 5; i++)
#pragma unroll
        for (int j = 0; j < 8; j++)
            p[(mg * 5 + i) * HH + n0 + 32 * j + nn] = acc[i][j];
}

// joint: all CTAs, reduce 32 pn partials + bias + tnproj -> tanh
__device__ void joint_stage(const float* __restrict__ b_joint, int t, int blk) {
    for (int e = blk * 256 + threadIdx.x; e < MM * HH; e += GRID_ALL * 256) {
        int m = e >> 10, j = e & 1023;
        float v = b_joint[j];
#pragma unroll
        for (int s = 0; s < 32; s++) v += g_bufB[(size_t)s * MM * HH + e];
        int b = m / KBM;
        v += g_tnproj[((size_t)b * TT + t) * HH + j];
        g_joint[e] = tanhf(v);
    }
}

// out: 16 col-blocks(256) x 16 k-splits(64) = 256 CTAs, 2 chunks of 32.
__device__ void out_stage(Smem* sm, int blk, const float* __restrict__ Wout) {
    int tid = threadIdx.x;
    int cb = blk & 15, sp = blk >> 4;
    int n0 = cb * 256, kb0 = sp * 64;

    auto stage = [&](int c) {
        int kg = kb0 + c * 32;
        int buf = c & 1;
#pragma unroll
        for (int r = 0; r < 5; r++) {
            int idx = tid + r * 256;
            int m = idx >> 5, kk = idx & 31;
            cpa4(&sm->As[buf][kk][m], &g_joint[m * HH + kg + kk]);
        }
#pragma unroll
        for (int r = 0; r < 8; r++) {
            int idx = tid + r * 256;
            int kk = idx >> 6, nq = (idx & 63) * 4;
            cpa16(&sm->Bs[buf][kk][nq], &Wout[(size_t)(kg + kk) * VV + n0 + nq]);
        }
        CPA_COMMIT();
    };

    float acc[5][8];
#pragma unroll
    for (int i = 0; i < 5; i++)
#pragma unroll
        for (int j = 0; j < 8; j++) acc[i][j] = 0.0f;
    int nn = tid & 31, mg = tid >> 5;

    stage(0);
    for (int c = 0; c < 2; c++) {
        if (c + 1 < 2) { stage(c + 1); CPA_WAIT(1); }
        else           { CPA_WAIT(0); }
        __syncthreads();
        mm_compute(sm->As[c & 1], sm->Bs[c & 1], acc, nn, mg);
        __syncthreads();
    }
    float* p = g_bufA + (size_t)sp * MM * VV;
#pragma unroll
    for (int i = 0; i < 5; i++)
#pragma unroll
        for (int j = 0; j < 8; j++)
            p[(mg * 5 + i) * VV + n0 + 32 * j + nn] = acc[i][j];
}

// stats: all CTAs. 5120 (row, 32-col slice) tasks: reduce 16 partials + bias,
// slice max / sumexp / top-5 -> global.
__device__ void stats_stage(int blk, const float* __restrict__ bout) {
    int warp = threadIdx.x >> 5, lane = threadIdx.x & 31;
    unsigned full = 0xffffffffu;
    for (int tk = blk * 8 + warp; tk < MM * 128; tk += GRID_ALL * 8) {
        int row = tk >> 7, sl = tk & 127;
        int col = sl * 32 + lane;
        float v = bout[col];
#pragma unroll
        for (int sp = 0; sp < 16; sp++)
            v += g_bufA[(size_t)sp * MM * VV + (size_t)row * VV + col];
        float mx = v;
#pragma unroll
        for (int off = 16; off > 0; off >>= 1)
            mx = fmaxf(mx, __shfl_xor_sync(full, mx, off));
        float se = expf(v - mx);
#pragma unroll
        for (int off = 16; off > 0; off >>= 1)
            se += __shfl_xor_sync(full, se, off);
        bool chosen = false;
        for (int j = 0; j < KBM; j++) {
            float cv = chosen ? NEGF : v;
            int ci = col;
#pragma unroll
            for (int off = 16; off > 0; off >>= 1) {
                float ov = __shfl_xor_sync(full, cv, off);
                int   oi = __shfl_xor_sync(full, ci, off);
                if (ov > cv || (ov == cv && oi < ci)) { cv = ov; ci = oi; }
            }
            if (lane == 0) {
                g_t5v[row * 640 + sl * 5 + j] = cv;
                g_t5i[row * 640 + sl * 5 + j] = ci;
            }
            if (col == ci) chosen = true;
        }
        if (lane == 0) { g_rmax[row * 128 + sl] = mx; g_rsum[row * 128 + sl] = se; }
    }
}

// topk merge + state update: 8 CTAs (one per batch).
__device__ void topk_stage(int b, int cur) {
    int tid = threadIdx.x;
    int nxt = cur ^ 1;
    int warp = tid >> 5, lane = tid & 31;
    unsigned full = 0xffffffffu;
    __shared__ float t_rv[25];
    __shared__ int   t_ri[25];
    __shared__ float t_fv[KBM];
    __shared__ int   t_fi[KBM];
    __shared__ int   t_par[KBM], t_tok[KBM], t_blk2[KBM], t_plen[KBM];

    if (warp < KBM) {
        int row = b * KBM + warp;
        float rm[4], rs[4];
#pragma unroll
        for (int q = 0; q < 4; q++) {
            rm[q] = g_rmax[row * 128 + lane * 4 + q];
            rs[q] = g_rsum[row * 128 + lane * 4 + q];
        }
        float M = fmaxf(fmaxf(rm[0], rm[1]), fmaxf(rm[2], rm[3]));
#pragma unroll
        for (int off = 16; off > 0; off >>= 1)
            M = fmaxf(M, __shfl_xor_sync(full, M, off));
        float S = 0.f;
#pragma unroll
        for (int q = 0; q < 4; q++) S += rs[q] * expf(rm[q] - M);
#pragma unroll
        for (int off = 16; off > 0; off >>= 1)
            S += __shfl_xor_sync(full, S, off);
        float lse = M + logf(S);
        float sc = g_scores[cur][row];
        int selg[KBM]; float selv[KBM];
        for (int j = 0; j < KBM; j++) {
            float bv = NEGF; int bi = 0x7fffffff;
            for (int q = 0; q < 20; q++) {
                int c = lane * 20 + q;
                int gidx = warp * 4096 + g_t5i[row * 640 + c];
                bool skip = false;
                for (int p = 0; p < j; p++) if (gidx == selg[p]) skip = true;
                if (skip) continue;
                float adj = sc + g_t5v[row * 640 + c] - lse;
                if (adj > bv || (adj == bv && gidx < bi)) { bv = adj; bi = gidx; }
            }
#pragma unroll
            for (int off = 16; off > 0; off >>= 1) {
                float ov = __shfl_xor_sync(full, bv, off);
                int   oi = __shfl_xor_sync(full, bi, off);
                if (ov > bv || (ov == bv && oi < bi)) { bv = ov; bi = oi; }
            }
            selg[j] = bi; selv[j] = bv;
        }
        if (lane == 0) {
#pragma unroll
            for (int j = 0; j < KBM; j++) {
                t_rv[warp * KBM + j] = selv[j];
                t_ri[warp * KBM + j] = selg[j];
            }
        }
    }
    __syncthreads();
    if (warp == 0) {
        float v  = (lane < 25) ? t_rv[lane] : NEGF;
        int   gi = (lane < 25) ? t_ri[lane] : 0x7fffffff;
        bool chosen = false;
        for (int j = 0; j < KBM; j++) {
            float cv = chosen ? NEGF : v;
            int ci = gi;
#pragma unroll
            for (int off = 16; off > 0; off >>= 1) {
                float ov = __shfl_xor_sync(full, cv, off);
                int   oi = __shfl_xor_sync(full, ci, off);
                if (ov > cv || (ov == cv && oi < ci)) { cv = ov; ci = oi; }
            }
            if (lane == 0) { t_fv[j] = cv; t_fi[j] = ci; }
            if (gi == ci) chosen = true;
        }
    }
    __syncthreads();
    if (tid < KBM) {
        int idx = t_fi[tid];
        int par = idx >> 12, tok = idx & 4095;
        int blank = (tok == 0);
        int p = b * KBM + par, mn = b * KBM + tid;
        t_par[tid] = par; t_tok[tid] = tok; t_blk2[tid] = blank;
        int pl = g_lens[cur][p];
        t_plen[tid] = pl;
        g_scores[nxt][mn] = t_fv[tid];
        g_lens[nxt][mn]   = pl + (blank ? 0 : 1);
        g_tokens[nxt][mn] = blank ? g_tokens[cur][p] : tok;
    }
    __syncthreads();
    for (int j = 0; j < KBM; j++) {
        int p = b * KBM + t_par[j], mn = b * KBM + j;
        bool blank = (t_blk2[j] != 0);
        const float* hs = blank ? &g_h[cur][p * HH] : &g_hnew[p * HH];
        const float* cs = blank ? &g_c[cur][p * HH] : &g_cnew[p * HH];
        for (int i = tid; i < HH; i += 256) {
            g_h[nxt][mn * HH + i] = hs[i];
            g_c[nxt][mn * HH + i] = cs[i];
        }
        for (int i = tid; i < TT; i += 256) {
            int v = g_preds[cur][p * TT + i];
            if (!blank && i == t_plen[j]) v = t_tok[j];
            g_preds[nxt][mn * TT + i] = v;
        }
    }
}

// ----------------------------- finalize -------------------------------------
__device__ void finalize_stage(float* __restrict__ out) {
    int tid = threadIdx.x;
    __shared__ float s_norm[MM];
    __shared__ int   s_best[BB];
    if (tid < MM)
        s_norm[tid] = g_scores[0][tid] / ((float)g_lens[0][tid] + 1.0f);
    __syncthreads();
    if (tid < BB) {
        float bv = NEGF; int bj = 0;
        for (int j = 0; j < KBM; j++) {
            float v = s_norm[tid * KBM + j];
            if (v > bv) { bv = v; bj = j; }
        }
        s_best[tid] = bj;
        out[BB * TT + tid] = (float)g_lens[0][tid * KBM + bj];
    }
    if (tid < MM) out[BB * TT + BB + 1 + tid] = s_norm[tid];
    __syncthreads();
    if (tid == 0) {
        float acc = 0.0f;
        for (int b2 = 0; b2 < BB; b2++) {
            float bv = NEGF;
            for (int j = 0; j < KBM; j++) bv = fmaxf(bv, s_norm[b2 * KBM + j]);
            acc += expf(bv);
        }
        out[BB * TT + BB] = acc / (float)BB;
    }
    for (int b2 = 0; b2 < BB; b2++) {
        int m = b2 * KBM + s_best[b2];
        for (int i = tid; i < TT; i += 256)
            out[b2 * TT + i] = (float)g_preds[0][m * TT + i];
    }
}

// ----------------------------- persistent kernel ----------------------------
__global__ __launch_bounds__(256, 2) void persist(const float* __restrict__ E,
                                                  const float* __restrict__ Wpn,
                                                  const float* __restrict__ b_joint,
                                                  const float* __restrict__ Wout,
                                                  const float* __restrict__ bout,
                                                  float* __restrict__ out) {
    __shared__ Smem sm;
    unsigned int ph = 0;
    int blk = blockIdx.x;
    for (int t = 0; t < TT; t++) {
        int cur = t & 1;
        if (blk < 256) gates_stage(&sm, blk, cur, E);
        gbar(ph);
        if (blk < 128) pn_stage(&sm, blk, cur, Wpn);
        gbar(ph);
        joint_stage(b_joint, t, blk);
        gbar(ph);
        if (blk < 256) out_stage(&sm, blk, Wout);
        gbar(ph);
        stats_stage(blk, bout);
        gbar(ph);
        if (blk < BB) topk_stage(blk, cur);
        gbar(ph);
    }
    if (blk == 0) finalize_stage(out);
}

// ----------------------------- launch ---------------------------------------
extern "C" void kernel_launch(void* const* d_in, const int* in_sizes, int n_in,
                              void* d_out, int out_size) {
    const float* tn      = (const float*)d_in[0];
    const float* E       = (const float*)d_in[1];
    const float* W_ih    = (const float*)d_in[2];
    const float* W_hh    = (const float*)d_in[3];
    const float* b_lstm  = (const float*)d_in[4];
    const float* W_tn    = (const float*)d_in[5];
    const float* W_pn    = (const float*)d_in[6];
    const float* b_joint = (const float*)d_in[7];
    const float* W_out   = (const float*)d_in[8];
    const float* b_out   = (const float*)d_in[9];
    float* out = (float*)d_out;

    init_state<<<160, 256>>>(b_lstm);
    permute_w<<<dim3(64, 128), dim3(32, 8)>>>(W_ih, W_hh);
    tnproj_gemm<<<dim3(16, 16), 256>>>(tn, W_tn);
    persist<<<GRID_ALL, 256>>>(E, W_pn, b_joint, W_out, b_out, out);
}

// round 7
// speedup vs baseline: 3.0011x; 1.0991x over previous
#include <cuda_runtime.h>
#include <cuda_bf16.h>
#include <cstdint>
#include <cstddef>

// RNN-T beam search. B=8, T=128, H=1024, V=4096, K=5 (M = 40 hyps).
// Persistent kernel, 2 CTAs/SM, cp.async double-buffered split-K GEMMs,
// packed fma.rn.f32x2 (FFMA2) inner loops.

#define HH   1024
#define VV   4096
#define BB   8
#define KBM  5
#define MM   40
#define TT   128
#define GRID_ALL 296
#define NEGF -3.0e38f

typedef unsigned long long u64;

// ----------------------------- device state --------------------------------
__device__ __align__(16) float g_tnproj[BB * TT * HH];     // 4 MB
__device__ __align__(16) float g_WcatT[2048 * 4096];       // 32 MB [k][n'] gate-permuted
__device__ __align__(16) float g_blstm_p[4096];            // permuted bias [4u+g]
__device__ __align__(16) float g_bufA[16 * MM * VV];       // gates/out partials (16 slices)
__device__ __align__(16) float g_bufB[32 * MM * HH];       // pn partials
__device__ __align__(16) float g_h[2][MM * HH];
__device__ __align__(16) float g_c[2][MM * HH];
__device__ __align__(16) float g_hnew[MM * HH];
__device__ __align__(16) float g_cnew[MM * HH];
__device__ __align__(16) float g_joint[MM * HH];
__device__ float g_rmax[MM * 128];
__device__ float g_rsum[MM * 128];
__device__ float g_t5v[MM * 640];
__device__ int   g_t5i[MM * 640];
__device__ float g_scores[2][MM];
__device__ int   g_tokens[2][MM];
__device__ int   g_lens[2][MM];
__device__ int   g_preds[2][MM * TT];
__device__ unsigned int g_barcnt;

__device__ __forceinline__ float sigm(float x) { return 1.0f / (1.0f + expf(-x)); }

// ----------------------------- packed f32x2 ---------------------------------
__device__ __forceinline__ u64 pk2(float a) {
    u64 r;
    asm("mov.b64 %0, {%1, %1};" : "=l"(r) : "f"(a));
    return r;
}
__device__ __forceinline__ void fma2(u64& d, u64 a, u64 b) {
    asm("fma.rn.f32x2 %0, %1, %2, %0;" : "+l"(d) : "l"(a), "l"(b));
}

// ----------------------------- cp.async helpers -----------------------------
__device__ __forceinline__ void cpa16(void* s, const void* g) {
    uint32_t sa = (uint32_t)__cvta_generic_to_shared(s);
    asm volatile("cp.async.cg.shared.global [%0], [%1], 16;" :: "r"(sa), "l"(g));
}
#define CPA_COMMIT()  asm volatile("cp.async.commit_group;" ::: "memory")
#define CPA_WAIT(N)   asm volatile("cp.async.wait_group %0;" :: "n"(N) : "memory")

// ---------------------- grid barrier (monotonic counter) --------------------
__device__ __forceinline__ void gbar(unsigned int& ph) {
    __syncthreads();
    ph++;
    if (threadIdx.x == 0) {
        __threadfence();
        atomicAdd(&g_barcnt, 1u);
        unsigned int target = ph * (unsigned int)GRID_ALL;
        while (*(volatile unsigned int*)&g_barcnt < target) __nanosleep(32);
        __threadfence();
    }
    __syncthreads();
}

// ----------------------------- init ----------------------------------------
__global__ void init_state(const float* __restrict__ b_lstm) {
    int idx = blockIdx.x * 256 + threadIdx.x;   // 160*256 = 40960
    if (idx < MM * HH) { g_h[0][idx] = 0.0f; g_c[0][idx] = 0.0f; }
    if (idx < MM) {
        g_scores[0][idx] = (idx % KBM == 0) ? 0.0f : -1e9f;
        g_tokens[0][idx] = 0;
        g_lens[0][idx]   = 0;
    }
    if (idx < MM * TT) g_preds[0][idx] = 0;
    if (idx < 4096) g_blstm_p[idx] = b_lstm[(idx & 3) * 1024 + (idx >> 2)];
    if (idx == 0) g_barcnt = 0u;
}

// --------------------- weight transpose + gate permute ----------------------
__global__ void permute_w(const float* __restrict__ Wih,
                          const float* __restrict__ Whh) {
    __shared__ float tile[32][33];
    int x = threadIdx.x, y0 = threadIdx.y;
    int kt = blockIdx.x * 32, nt = blockIdx.y * 32;
#pragma unroll
    for (int yy = 0; yy < 32; yy += 8) {
        int np = nt + y0 + yy;
        int row = (np & 3) * 1024 + (np >> 2);
        int k = kt + x;
        float v = (k < 1024) ? Wih[(size_t)row * 1024 + k]
                             : Whh[(size_t)row * 1024 + k - 1024];
        tile[y0 + yy][x] = v;
    }
    __syncthreads();
#pragma unroll
    for (int yy = 0; yy < 32; yy += 8) {
        int k = kt + y0 + yy;
        int np = nt + x;
        g_WcatT[(size_t)k * 4096 + np] = tile[x][y0 + yy];
    }
}

// ----------------------------- tn_proj GEMM --------------------------------
__global__ __launch_bounds__(256) void tnproj_gemm(const float* __restrict__ A,
                                                   const float* __restrict__ Bm) {
    __shared__ float As[16][65];
    __shared__ float Bs[16][64];
    int tid = threadIdx.x;
    int tx = tid & 15, ty = tid >> 4;
    int m0 = blockIdx.y * 64, n0 = blockIdx.x * 64;
    float acc[4][4];
#pragma unroll
    for (int i = 0; i < 4; i++)
#pragma unroll
        for (int j = 0; j < 4; j++) acc[i][j] = 0.0f;
    for (int kk = 0; kk < 1024; kk += 16) {
        {
            int mm = tid >> 2;
            int kq = (tid & 3) * 4;
            float4 v = *(const float4*)&A[(size_t)(m0 + mm) * 1024 + kk + kq];
            As[kq + 0][mm] = v.x; As[kq + 1][mm] = v.y;
            As[kq + 2][mm] = v.z; As[kq + 3][mm] = v.w;
        }
#pragma unroll
        for (int r = 0; r < 4; r++) {
            int idx = tid + r * 256;
            int k = idx >> 6, n = idx & 63;
            Bs[k][n] = Bm[(size_t)(kk + k) * 1024 + n0 + n];
        }
        __syncthreads();
#pragma unroll
        for (int k = 0; k < 16; k++) {
            float a[4], b[4];
#pragma unroll
            for (int i = 0; i < 4; i++) a[i] = As[k][ty + 16 * i];
#pragma unroll
            for (int j = 0; j < 4; j++) b[j] = Bs[k][tx + 16 * j];
#pragma unroll
            for (int i = 0; i < 4; i++)
#pragma unroll
                for (int j = 0; j < 4; j++) acc[i][j] += a[i] * b[j];
        }
        __syncthreads();
    }
#pragma unroll
    for (int i = 0; i < 4; i++)
#pragma unroll
        for (int j = 0; j < 4; j++)
            g_tnproj[(size_t)(m0 + ty + 16 * i) * 1024 + n0 + tx + 16 * j] = acc[i][j];
}

// =========================== persistent stages ==============================
struct Smem {
    float As[2][MM][32];      // [m][k] chunk
    float Bs[2][32][256];     // [k][n] chunk
    int   tok[MM];
};

// FFMA2 inner product over one 32-k chunk. Thread owns column pairs
// {nn2+64j, nn2+64j+1}, j=0..3, rows mg*5..mg*5+4.
__device__ __forceinline__ void mm_compute2(const float (*As)[32], const float (*Bs)[256],
                                            u64 acc[5][4], int nn2, int mg) {
#pragma unroll 4
    for (int kk = 0; kk < 32; kk++) {
        u64 b[4];
#pragma unroll
        for (int j = 0; j < 4; j++) b[j] = *(const u64*)&Bs[kk][nn2 + 64 * j];
#pragma unroll
        for (int i = 0; i < 5; i++) {
            u64 a2 = pk2(As[mg * 5 + i][kk]);
#pragma unroll
            for (int j = 0; j < 4; j++) fma2(acc[i][j], a2, b[j]);
        }
    }
}

// gates: 16 col-blocks(256) x 16 k-splits(128) = 256 CTAs, 4 chunks of 32.
__device__ void gates_stage(Smem* sm, int blk, int cur, const float* __restrict__ E) {
    int tid = threadIdx.x;
    int cb = blk & 15, sp = blk >> 4;
    int n0 = cb * 256, kb0 = sp * 128;
    if (tid < MM) sm->tok[tid] = g_tokens[cur][tid];
    __syncthreads();

    auto stage = [&](int c) {
        int kg = kb0 + c * 32;
        int buf = c & 1;
        // A: 40 rows x 32 k = 320 float4 copies, strided over 256 threads
#pragma unroll
        for (int r = 0; r < 2; r++) {
            int idx = tid + r * 256;
            if (idx < 320) {
                int m = idx >> 3, q = (idx & 7) * 4;
                const float* src = (sp < 8)
                    ? &E[(size_t)sm->tok[m] * HH + kg + q]
                    : &g_h[cur][m * HH + (kg + q - 1024)];
                cpa16(&sm->As[buf][m][q], src);
            }
        }
#pragma unroll
        for (int r = 0; r < 8; r++) {
            int idx = tid + r * 256;
            int kk = idx >> 6, nq = (idx & 63) * 4;
            cpa16(&sm->Bs[buf][kk][nq], &g_WcatT[(size_t)(kg + kk) * 4096 + n0 + nq]);
        }
        CPA_COMMIT();
    };

    u64 acc[5][4];
#pragma unroll
    for (int i = 0; i < 5; i++)
#pragma unroll
        for (int j = 0; j < 4; j++) acc[i][j] = 0ull;
    int nn2 = (tid & 31) * 2, mg = tid >> 5;

    stage(0);
    for (int c = 0; c < 4; c++) {
        if (c + 1 < 4) { stage(c + 1); CPA_WAIT(1); }
        else           { CPA_WAIT(0); }
        __syncthreads();
        mm_compute2(sm->As[c & 1], sm->Bs[c & 1], acc, nn2, mg);
        __syncthreads();
    }
    float* p = g_bufA + (size_t)sp * MM * VV;
#pragma unroll
    for (int i = 0; i < 5; i++)
#pragma unroll
        for (int j = 0; j < 4; j++)
            *(u64*)&p[(mg * 5 + i) * VV + n0 + 64 * j + nn2] = acc[i][j];
}

// pn: 4 col-blocks(256) x 32 k-splits(32) = 128 CTAs. LSTM-reduce prologue.
__device__ void pn_stage(Smem* sm, int blk, int cur, const float* __restrict__ Wpn) {
    int tid = threadIdx.x;
    int cb = blk & 3, s = blk >> 2;
    int n0 = cb * 256, kl = s * 32;

#pragma unroll
    for (int r = 0; r < 8; r++) {
        int idx = tid + r * 256;
        int kk = idx >> 6, nq = (idx & 63) * 4;
        cpa16(&sm->Bs[0][kk][nq], &Wpn[(size_t)(kl + kk) * HH + n0 + nq]);
    }
    CPA_COMMIT();

    // LSTM prologue: hnew for (m, u=kl..kl+31) -> As[0][m][kk]
#pragma unroll
    for (int r = 0; r < 5; r++) {
        int idx = tid + r * 256;
        int m = idx >> 5, kk = idx & 31;
        int u = kl + kk;
        float4 s4 = make_float4(0.f, 0.f, 0.f, 0.f);
#pragma unroll
        for (int sp = 0; sp < 16; sp++) {
            float4 q = *(const float4*)&g_bufA[(size_t)sp * MM * VV + m * VV + 4 * u];
            s4.x += q.x; s4.y += q.y; s4.z += q.z; s4.w += q.w;
        }
        float4 bb = *(const float4*)&g_blstm_p[4 * u];
        float gi = s4.x + bb.x, gf = s4.y + bb.y, gg = s4.z + bb.z, go = s4.w + bb.w;
        float co = g_c[cur][m * HH + u];
        float cn = sigm(gf) * co + sigm(gi) * tanhf(gg);
        float hn = sigm(go) * tanhf(cn);
        sm->As[0][m][kk] = hn;
        if (cb == 0) { g_hnew[m * HH + u] = hn; g_cnew[m * HH + u] = cn; }
    }
    CPA_WAIT(0);
    __syncthreads();

    u64 acc[5][4];
#pragma unroll
    for (int i = 0; i < 5; i++)
#pragma unroll
        for (int j = 0; j < 4; j++) acc[i][j] = 0ull;
    int nn2 = (tid & 31) * 2, mg = tid >> 5;
    mm_compute2(sm->As[0], sm->Bs[0], acc, nn2, mg);
    __syncthreads();

    float* p = g_bufB + (size_t)s * MM * HH;
#pragma unroll
    for (int i = 0; i < 5; i++)
#pragma unroll
        for (int j = 0; j < 4; j++)
            *(u64*)&p[(mg * 5 + i) * HH + n0 + 64 * j + nn2] = acc[i][j];
}

// joint: all CTAs, reduce 32 pn partials + bias + tnproj -> tanh
__device__ void joint_stage(const float* __restrict__ b_joint, int t, int blk) {
    for (int e = blk * 256 + threadIdx.x; e < MM * HH; e += GRID_ALL * 256) {
        int m = e >> 10, j = e & 1023;
        float v = b_joint[j];
#pragma unroll
        for (int s = 0; s < 32; s++) v += g_bufB[(size_t)s * MM * HH + e];
        int b = m / KBM;
        v += g_tnproj[((size_t)b * TT + t) * HH + j];
        g_joint[e] = tanhf(v);
    }
}

// out: 16 col-blocks(256) x 16 k-splits(64) = 256 CTAs, 2 chunks of 32.
__device__ void out_stage(Smem* sm, int blk, const float* __restrict__ Wout) {
    int tid = threadIdx.x;
    int cb = blk & 15, sp = blk >> 4;
    int n0 = cb * 256, kb0 = sp * 64;

    auto stage = [&](int c) {
        int kg = kb0 + c * 32;
        int buf = c & 1;
#pragma unroll
        for (int r = 0; r < 2; r++) {
            int idx = tid + r * 256;
            if (idx < 320) {
                int m = idx >> 3, q = (idx & 7) * 4;
                cpa16(&sm->As[buf][m][q], &g_joint[m * HH + kg + q]);
            }
        }
#pragma unroll
        for (int r = 0; r < 8; r++) {
            int idx = tid + r * 256;
            int kk = idx >> 6, nq = (idx & 63) * 4;
            cpa16(&sm->Bs[buf][kk][nq], &Wout[(size_t)(kg + kk) * VV + n0 + nq]);
        }
        CPA_COMMIT();
    };

    u64 acc[5][4];
#pragma unroll
    for (int i = 0; i < 5; i++)
#pragma unroll
        for (int j = 0; j < 4; j++) acc[i][j] = 0ull;
    int nn2 = (tid & 31) * 2, mg = tid >> 5;

    stage(0);
    for (int c = 0; c < 2; c++) {
        if (c + 1 < 2) { stage(c + 1); CPA_WAIT(1); }
        else           { CPA_WAIT(0); }
        __syncthreads();
        mm_compute2(sm->As[c & 1], sm->Bs[c & 1], acc, nn2, mg);
        __syncthreads();
    }
    float* p = g_bufA + (size_t)sp * MM * VV;
#pragma unroll
    for (int i = 0; i < 5; i++)
#pragma unroll
        for (int j = 0; j < 4; j++)
            *(u64*)&p[(mg * 5 + i) * VV + n0 + 64 * j + nn2] = acc[i][j];
}

// stats: all CTAs. 5120 (row, 32-col slice) tasks.
__device__ void stats_stage(int blk, const float* __restrict__ bout) {
    int warp = threadIdx.x >> 5, lane = threadIdx.x & 31;
    unsigned full = 0xffffffffu;
    for (int tk = blk * 8 + warp; tk < MM * 128; tk += GRID_ALL * 8) {
        int row = tk >> 7, sl = tk & 127;
        int col = sl * 32 + lane;
        float v = bout[col];
#pragma unroll
        for (int sp = 0; sp < 16; sp++)
            v += g_bufA[(size_t)sp * MM * VV + (size_t)row * VV + col];
        float mx = v;
#pragma unroll
        for (int off = 16; off > 0; off >>= 1)
            mx = fmaxf(mx, __shfl_xor_sync(full, mx, off));
        float se = expf(v - mx);
#pragma unroll
        for (int off = 16; off > 0; off >>= 1)
            se += __shfl_xor_sync(full, se, off);
        bool chosen = false;
        for (int j = 0; j < KBM; j++) {
            float cv = chosen ? NEGF : v;
            int ci = col;
#pragma unroll
            for (int off = 16; off > 0; off >>= 1) {
                float ov = __shfl_xor_sync(full, cv, off);
                int   oi = __shfl_xor_sync(full, ci, off);
                if (ov > cv || (ov == cv && oi < ci)) { cv = ov; ci = oi; }
            }
            if (lane == 0) {
                g_t5v[row * 640 + sl * 5 + j] = cv;
                g_t5i[row * 640 + sl * 5 + j] = ci;
            }
            if (col == ci) chosen = true;
        }
        if (lane == 0) { g_rmax[row * 128 + sl] = mx; g_rsum[row * 128 + sl] = se; }
    }
}

// topk merge + state update: 8 CTAs (one per batch).
__device__ void topk_stage(int b, int cur) {
    int tid = threadIdx.x;
    int nxt = cur ^ 1;
    int warp = tid >> 5, lane = tid & 31;
    unsigned full = 0xffffffffu;
    __shared__ float t_rv[25];
    __shared__ int   t_ri[25];
    __shared__ float t_fv[KBM];
    __shared__ int   t_fi[KBM];
    __shared__ int   t_par[KBM], t_tok[KBM], t_blk2[KBM], t_plen[KBM];

    if (warp < KBM) {
        int row = b * KBM + warp;
        float rm[4], rs[4];
#pragma unroll
        for (int q = 0; q < 4; q++) {
            rm[q] = g_rmax[row * 128 + lane * 4 + q];
            rs[q] = g_rsum[row * 128 + lane * 4 + q];
        }
        float M = fmaxf(fmaxf(rm[0], rm[1]), fmaxf(rm[2], rm[3]));
#pragma unroll
        for (int off = 16; off > 0; off >>= 1)
            M = fmaxf(M, __shfl_xor_sync(full, M, off));
        float S = 0.f;
#pragma unroll
        for (int q = 0; q < 4; q++) S += rs[q] * expf(rm[q] - M);
#pragma unroll
        for (int off = 16; off > 0; off >>= 1)
            S += __shfl_xor_sync(full, S, off);
        float lse = M + logf(S);
        float sc = g_scores[cur][row];
        int selg[KBM]; float selv[KBM];
        for (int j = 0; j < KBM; j++) {
            float bv = NEGF; int bi = 0x7fffffff;
            for (int q = 0; q < 20; q++) {
                int c = lane * 20 + q;
                int gidx = warp * 4096 + g_t5i[row * 640 + c];
                bool skip = false;
                for (int p = 0; p < j; p++) if (gidx == selg[p]) skip = true;
                if (skip) continue;
                float adj = sc + g_t5v[row * 640 + c] - lse;
                if (adj > bv || (adj == bv && gidx < bi)) { bv = adj; bi = gidx; }
            }
#pragma unroll
            for (int off = 16; off > 0; off >>= 1) {
                float ov = __shfl_xor_sync(full, bv, off);
                int   oi = __shfl_xor_sync(full, bi, off);
                if (ov > bv || (ov == bv && oi < bi)) { bv = ov; bi = oi; }
            }
            selg[j] = bi; selv[j] = bv;
        }
        if (lane == 0) {
#pragma unroll
            for (int j = 0; j < KBM; j++) {
                t_rv[warp * KBM + j] = selv[j];
                t_ri[warp * KBM + j] = selg[j];
            }
        }
    }
    __syncthreads();
    if (warp == 0) {
        float v  = (lane < 25) ? t_rv[lane] : NEGF;
        int   gi = (lane < 25) ? t_ri[lane] : 0x7fffffff;
        bool chosen = false;
        for (int j = 0; j < KBM; j++) {
            float cv = chosen ? NEGF : v;
            int ci = gi;
#pragma unroll
            for (int off = 16; off > 0; off >>= 1) {
                float ov = __shfl_xor_sync(full, cv, off);
                int   oi = __shfl_xor_sync(full, ci, off);
                if (ov > cv || (ov == cv && oi < ci)) { cv = ov; ci = oi; }
            }
            if (lane == 0) { t_fv[j] = cv; t_fi[j] = ci; }
            if (gi == ci) chosen = true;
        }
    }
    __syncthreads();
    if (tid < KBM) {
        int idx = t_fi[tid];
        int par = idx >> 12, tok = idx & 4095;
        int blank = (tok == 0);
        int p = b * KBM + par, mn = b * KBM + tid;
        t_par[tid] = par; t_tok[tid] = tok; t_blk2[tid] = blank;
        int pl = g_lens[cur][p];
        t_plen[tid] = pl;
        g_scores[nxt][mn] = t_fv[tid];
        g_lens[nxt][mn]   = pl + (blank ? 0 : 1);
        g_tokens[nxt][mn] = blank ? g_tokens[cur][p] : tok;
    }
    __syncthreads();
    for (int j = 0; j < KBM; j++) {
        int p = b * KBM + t_par[j], mn = b * KBM + j;
        bool blank = (t_blk2[j] != 0);
        const float* hs = blank ? &g_h[cur][p * HH] : &g_hnew[p * HH];
        const float* cs = blank ? &g_c[cur][p * HH] : &g_cnew[p * HH];
        for (int i = tid; i < HH; i += 256) {
            g_h[nxt][mn * HH + i] = hs[i];
            g_c[nxt][mn * HH + i] = cs[i];
        }
        for (int i = tid; i < TT; i += 256) {
            int v = g_preds[cur][p * TT + i];
            if (!blank && i == t_plen[j]) v = t_tok[j];
            g_preds[nxt][mn * TT + i] = v;
        }
    }
}

// ----------------------------- finalize -------------------------------------
__device__ void finalize_stage(float* __restrict__ out) {
    int tid = threadIdx.x;
    __shared__ float s_norm[MM];
    __shared__ int   s_best[BB];
    if (tid < MM)
        s_norm[tid] = g_scores[0][tid] / ((float)g_lens[0][tid] + 1.0f);
    __syncthreads();
    if (tid < BB) {
        float bv = NEGF; int bj = 0;
        for (int j = 0; j < KBM; j++) {
            float v = s_norm[tid * KBM + j];
            if (v > bv) { bv = v; bj = j; }
        }
        s_best[tid] = bj;
        out[BB * TT + tid] = (float)g_lens[0][tid * KBM + bj];
    }
    if (tid < MM) out[BB * TT + BB + 1 + tid] = s_norm[tid];
    __syncthreads();
    if (tid == 0) {
        float acc = 0.0f;
        for (int b2 = 0; b2 < BB; b2++) {
            float bv = NEGF;
            for (int j = 0; j < KBM; j++) bv = fmaxf(bv, s_norm[b2 * KBM + j]);
            acc += expf(bv);
        }
        out[BB * TT + BB] = acc / (float)BB;
    }
    for (int b2 = 0; b2 < BB; b2++) {
        int m = b2 * KBM + s_best[b2];
        for (int i = tid; i < TT; i += 256)
            out[b2 * TT + i] = (float)g_preds[0][m * TT + i];
    }
}

// ----------------------------- persistent kernel ----------------------------
__global__ __launch_bounds__(256, 2) void persist(const float* __restrict__ E,
                                                  const float* __restrict__ Wpn,
                                                  const float* __restrict__ b_joint,
                                                  const float* __restrict__ Wout,
                                                  const float* __restrict__ bout,
                                                  float* __restrict__ out) {
    __shared__ Smem sm;
    unsigned int ph = 0;
    int blk = blockIdx.x;
    for (int t = 0; t < TT; t++) {
        int cur = t & 1;
        if (blk < 256) gates_stage(&sm, blk, cur, E);
        gbar(ph);
        if (blk < 128) pn_stage(&sm, blk, cur, Wpn);
        gbar(ph);
        joint_stage(b_joint, t, blk);
        gbar(ph);
        if (blk < 256) out_stage(&sm, blk, Wout);
        gbar(ph);
        stats_stage(blk, bout);
        gbar(ph);
        if (blk < BB) topk_stage(blk, cur);
        gbar(ph);
    }
    if (blk == 0) finalize_stage(out);
}

// ----------------------------- launch ---------------------------------------
extern "C" void kernel_launch(void* const* d_in, const int* in_sizes, int n_in,
                              void* d_out, int out_size) {
    const float* tn      = (const float*)d_in[0];
    const float* E       = (const float*)d_in[1];
    const float* W_ih    = (const float*)d_in[2];
    const float* W_hh    = (const float*)d_in[3];
    const float* b_lstm  = (const float*)d_in[4];
    const float* W_tn    = (const float*)d_in[5];
    const float* W_pn    = (const float*)d_in[6];
    const float* b_joint = (const float*)d_in[7];
    const float* W_out   = (const float*)d_in[8];
    const float* b_out   = (const float*)d_in[9];
    float* out = (float*)d_out;

    init_state<<<160, 256>>>(b_lstm);
    permute_w<<<dim3(64, 128), dim3(32, 8)>>>(W_ih, W_hh);
    tnproj_gemm<<<dim3(16, 16), 256>>>(tn, W_tn);
    persist<<<GRID_ALL, 256>>>(E, W_pn, b_joint, W_out, b_out, out);
}